// round 15
// baseline (speedup 1.0000x reference)
#include <cuda_runtime.h>
#include <cuda_bf16.h>
#include <cstdint>

// ---------------------------------------------------------------------------
// GRU_2602750181500: bidirectional GRU, T=2048, B=32, F=H=512, fp32.
// R15: recurrence restructured as 64 CTAs x 2 interleaved batch-group chains
//      (same w_hh SMEM serves both). Section A's handshake hides behind
//      section B's compute and vice versa. Per-warp red.release flag adds
//      (no block barrier on the cross-CTA path). Datapath per section =
//      R10/R11 proven pieces (wh reg frags, B-frags direct from L2, 2-stage
//      reduction double-buffered per section). GEMM/conv = R12 (best).
// ---------------------------------------------------------------------------

#define T_ 2048
#define B_ 32
#define H_ 512
#define G_ 1536

__device__ __forceinline__ unsigned ld_acquire(const unsigned* p) {
    unsigned v;
    asm volatile("ld.acquire.gpu.global.u32 %0, [%1];" : "=r"(v) : "l"(p) : "memory");
    return v;
}
__device__ __forceinline__ void red_release_add(unsigned* p, unsigned v) {
    asm volatile("red.release.gpu.global.add.u32 [%0], %1;" :: "l"(p), "r"(v) : "memory");
}
__device__ __forceinline__ uint32_t smem_u32(const void* p) {
    uint32_t a;
    asm("{ .reg .u64 t; cvta.to.shared.u64 t, %1; cvt.u32.u64 %0, t; }"
        : "=r"(a) : "l"(p));
    return a;
}
__device__ __forceinline__ void st_cg_u16(unsigned short* p, unsigned short v) {
    asm volatile("st.global.cg.u16 [%0], %1;" :: "l"(p), "h"(v) : "memory");
}
__device__ __forceinline__ uint32_t ld_cg_u32(const unsigned short* p) {
    uint32_t v;
    asm volatile("ld.global.cg.u32 %0, [%1];" : "=r"(v) : "l"(p));
    return v;
}

#define LDSM4(r, addr) \
    asm volatile("ldmatrix.sync.aligned.m8n8.x4.shared.b16 {%0,%1,%2,%3}, [%4];" \
        : "=r"((r)[0]), "=r"((r)[1]), "=r"((r)[2]), "=r"((r)[3]) : "r"(addr))

#define MMA_BF16(d, a, b0, b1) \
    asm volatile("mma.sync.aligned.m16n8k16.row.col.f32.bf16.bf16.f32 " \
        "{%0,%1,%2,%3}, {%4,%5,%6,%7}, {%8,%9}, {%0,%1,%2,%3};" \
        : "+f"((d)[0]), "+f"((d)[1]), "+f"((d)[2]), "+f"((d)[3]) \
        : "r"((a)[0]), "r"((a)[1]), "r"((a)[2]), "r"((a)[3]), "r"(b0), "r"(b1))

// Scratch (device globals: allocation-free rule).
__device__ float          g_gi[2][(size_t)T_ * B_ * G_];
__device__ unsigned short g_hh[2][4][2][8][512];   // [dir][bg][pp][b][k]
__device__ unsigned short g_hl[2][4][2][8][512];
__device__ unsigned       g_flags[2][4][16 * 8];
__device__ __nv_bfloat16  g_xh[(size_t)T_ * B_ * 512];
__device__ __nv_bfloat16  g_xl[(size_t)T_ * B_ * 512];
__device__ __nv_bfloat16  g_wh[2][(size_t)G_ * 512];
__device__ __nv_bfloat16  g_wl[2][(size_t)G_ * 512];

// ---------------------------------------------------------------------------
// Split-conversion.
// ---------------------------------------------------------------------------
__global__ void conv_split(const float4* __restrict__ src,
                           __nv_bfloat162* __restrict__ hi,
                           __nv_bfloat162* __restrict__ lo, int n4)
{
    int i = blockIdx.x * blockDim.x + threadIdx.x;
    if (i >= n4) return;
    float4 v = src[i];
    __nv_bfloat16 h0 = __float2bfloat16(v.x), h1 = __float2bfloat16(v.y);
    __nv_bfloat16 h2 = __float2bfloat16(v.z), h3 = __float2bfloat16(v.w);
    hi[2 * i]     = __nv_bfloat162(h0, h1);
    hi[2 * i + 1] = __nv_bfloat162(h2, h3);
    lo[2 * i]     = __nv_bfloat162(__float2bfloat16(v.x - __bfloat162float(h0)),
                                   __float2bfloat16(v.y - __bfloat162float(h1)));
    lo[2 * i + 1] = __nv_bfloat162(__float2bfloat16(v.z - __bfloat162float(h2)),
                                   __float2bfloat16(v.w - __bfloat162float(h3)));
}

// ---------------------------------------------------------------------------
// Kernel 1: gi GEMM via HMMA (R12 version, register-prefetch 2-stage).
// ---------------------------------------------------------------------------
#define PADB 40
#define ARRE (128 * PADB)
#define ARRB (ARRE * 2)
#define STGB (4 * ARRB)
#define GEMM_SMEM (2 * STGB)

__global__ void __launch_bounds__(256, 1) gi_gemm_tc(
    const float* __restrict__ bf, const float* __restrict__ br)
{
    extern __shared__ __nv_bfloat16 sm[];

    const int tid  = threadIdx.x;
    const int lane = tid & 31;
    const int warp = tid >> 5;
    const int dir  = blockIdx.z;
    const int n0   = blockIdx.x * 128;
    const int m0   = blockIdx.y * 128;

    const __nv_bfloat16* __restrict__ xh = g_xh;
    const __nv_bfloat16* __restrict__ xl = g_xl;
    const __nv_bfloat16* __restrict__ wh = g_wh[dir];
    const __nv_bfloat16* __restrict__ wl = g_wl[dir];
    const float* __restrict__ bias = dir ? br : bf;
    float* __restrict__ gi = g_gi[dir];

    const int r0 = tid >> 2;
    const int c8 = (tid & 3) * 8;
    const __nv_bfloat16* pxh = xh + (size_t)(m0 + r0) * 512 + c8;
    const __nv_bfloat16* pxl = xl + (size_t)(m0 + r0) * 512 + c8;
    const __nv_bfloat16* pwh = wh + (size_t)(n0 + r0) * 512 + c8;
    const __nv_bfloat16* pwl = wl + (size_t)(n0 + r0) * 512 + c8;
    const size_t rstep = (size_t)64 * 512;

    const int so0 = r0 * PADB + c8;
    const int so1 = (r0 + 64) * PADB + c8;

    const int wm = warp >> 2, wn = warp & 3;
    const int a_row = wm * 64 + (lane & 15);
    const int a_off = (a_row * PADB + (lane >> 4) * 8) * 2;
    const int b_row = wn * 32 + (lane & 7) + ((lane >> 4) << 3);
    const int b_off = (b_row * PADB + ((lane >> 3) & 1) * 8) * 2;

    const uint32_t smb = smem_u32(sm);

    float acc[4][4][4];
#pragma unroll
    for (int i = 0; i < 4; i++)
#pragma unroll
        for (int j = 0; j < 4; j++)
#pragma unroll
            for (int q = 0; q < 4; q++) acc[i][j][q] = 0.f;

    float4 vh0, vh1, vl0, vl1, uh0, uh1, ul0, ul1;
    vh0 = *(const float4*)(pxh); vh1 = *(const float4*)(pxh + rstep);
    vl0 = *(const float4*)(pxl); vl1 = *(const float4*)(pxl + rstep);
    uh0 = *(const float4*)(pwh); uh1 = *(const float4*)(pwh + rstep);
    ul0 = *(const float4*)(pwl); ul1 = *(const float4*)(pwl + rstep);
    *(float4*)&sm[0 * ARRE + so0] = vh0; *(float4*)&sm[0 * ARRE + so1] = vh1;
    *(float4*)&sm[1 * ARRE + so0] = vl0; *(float4*)&sm[1 * ARRE + so1] = vl1;
    *(float4*)&sm[2 * ARRE + so0] = uh0; *(float4*)&sm[2 * ARRE + so1] = uh1;
    *(float4*)&sm[3 * ARRE + so0] = ul0; *(float4*)&sm[3 * ARRE + so1] = ul1;
    __syncthreads();

    for (int c = 0; c < 16; c++) {
        const int st = c & 1;
        if (c < 15) {
            const int k0 = (c + 1) * 32;
            vh0 = *(const float4*)(pxh + k0); vh1 = *(const float4*)(pxh + k0 + rstep);
            vl0 = *(const float4*)(pxl + k0); vl1 = *(const float4*)(pxl + k0 + rstep);
            uh0 = *(const float4*)(pwh + k0); uh1 = *(const float4*)(pwh + k0 + rstep);
            ul0 = *(const float4*)(pwl + k0); ul1 = *(const float4*)(pwl + k0 + rstep);
        }

        const uint32_t sb = smb + st * STGB;
#pragma unroll
        for (int kk = 0; kk < 2; kk++) {
            const uint32_t kby = kk * 32;
            uint32_t ah[4][4], al[4][4], bh[2][4], bl[2][4];
#pragma unroll
            for (int mt = 0; mt < 4; mt++) {
                LDSM4(ah[mt], sb + 0 * ARRB + a_off + mt * (16 * PADB * 2) + kby);
                LDSM4(al[mt], sb + 1 * ARRB + a_off + mt * (16 * PADB * 2) + kby);
            }
#pragma unroll
            for (int np = 0; np < 2; np++) {
                LDSM4(bh[np], sb + 2 * ARRB + b_off + np * (16 * PADB * 2) + kby);
                LDSM4(bl[np], sb + 3 * ARRB + b_off + np * (16 * PADB * 2) + kby);
            }
#pragma unroll
            for (int mt = 0; mt < 4; mt++) {
#pragma unroll
                for (int nt = 0; nt < 4; nt++) {
                    const int np = nt >> 1, hf = (nt & 1) * 2;
                    MMA_BF16(acc[mt][nt], ah[mt], bh[np][hf], bh[np][hf + 1]);
                    MMA_BF16(acc[mt][nt], ah[mt], bl[np][hf], bl[np][hf + 1]);
                    MMA_BF16(acc[mt][nt], al[mt], bh[np][hf], bh[np][hf + 1]);
                }
            }
        }
        __syncthreads();
        if (c < 15) {
            const int os = (st ^ 1) * (STGB / 2);
            *(float4*)&sm[os + 0 * ARRE + so0] = vh0; *(float4*)&sm[os + 0 * ARRE + so1] = vh1;
            *(float4*)&sm[os + 1 * ARRE + so0] = vl0; *(float4*)&sm[os + 1 * ARRE + so1] = vl1;
            *(float4*)&sm[os + 2 * ARRE + so0] = uh0; *(float4*)&sm[os + 2 * ARRE + so1] = uh1;
            *(float4*)&sm[os + 3 * ARRE + so0] = ul0; *(float4*)&sm[os + 3 * ARRE + so1] = ul1;
            __syncthreads();
        }
    }

#pragma unroll
    for (int mt = 0; mt < 4; mt++) {
        const int m = m0 + wm * 64 + mt * 16 + (lane >> 2);
#pragma unroll
        for (int nt = 0; nt < 4; nt++) {
            const int n = n0 + wn * 32 + nt * 8 + (lane & 3) * 2;
            const float b0 = bias[n], b1 = bias[n + 1];
            *(float2*)&gi[(size_t)m * G_ + n] =
                make_float2(acc[mt][nt][0] + b0, acc[mt][nt][1] + b1);
            *(float2*)&gi[(size_t)(m + 8) * G_ + n] =
                make_float2(acc[mt][nt][2] + b0, acc[mt][nt][3] + b1);
        }
    }
}

// ---------------------------------------------------------------------------
// Kernel 2: recurrence, 64 CTAs x 2 interleaved batch-group sections.
// SMEM: wh [96][520] bf16 | wl [96][520] | red f32 [2 sec][4 q][960]
// ---------------------------------------------------------------------------
#define WST 520
#define WL_B  (96 * WST * 2)                 // 99840 bytes
#define RED_B (2 * WL_B)                     // 199680
#define SMEM_REC (RED_B + 2 * 4 * 960 * 4)   // 230400 bytes

__global__ void __launch_bounds__(256, 1) gru_rec(
    const float* __restrict__ h0,
    const float* __restrict__ whh_f, const float* __restrict__ bhh_f,
    const float* __restrict__ whh_r, const float* __restrict__ bhh_r,
    float* __restrict__ out, int out_size)
{
    extern __shared__ char smc[];
    __nv_bfloat16* swh = (__nv_bfloat16*)smc;
    __nv_bfloat16* swl = (__nv_bfloat16*)(smc + WL_B);
    float* red = (float*)(smc + RED_B);      // [2][4][960]

    const int tid  = threadIdx.x;
    const int warp = tid >> 5;
    const int lane = tid & 31;
    const int bid = blockIdx.x;              // 64 CTAs
    const int dir = bid >> 5;
    const int bp  = (bid >> 4) & 1;          // batch-pair: bgs {2bp, 2bp+1}
    const int sl  = bid & 15;

    const float* __restrict__ whh = dir ? whh_r : whh_f;
    const float* __restrict__ bhh = dir ? bhh_r : bhh_f;
    const float* __restrict__ gi  = g_gi[dir];

    const int bgA = 2 * bp, bgB = 2 * bp + 1;
    unsigned* gfl[2] = { &g_flags[dir][bgA][0], &g_flags[dir][bgB][0] };
    unsigned* fown[2] = { gfl[0] + sl * 8, gfl[1] + sl * 8 };
    unsigned basex[2];
    basex[0] = ld_acquire(fown[0]);
    basex[1] = ld_acquire(fown[1]);

    // w_hh slice -> SMEM as bf16 hi/lo (shared by both sections).
    for (int idx = tid; idx < 96 * 512; idx += 256) {
        int r = idx >> 9, k = idx & 511;
        float v = whh[(size_t)((r >> 5) * 512 + sl * 32 + (r & 31)) * 512 + k];
        __nv_bfloat16 h = __float2bfloat16(v);
        swh[r * WST + k] = h;
        swl[r * WST + k] = __float2bfloat16(v - __bfloat162float(h));
    }

    const int il = lane;
    const int iglob = sl * 32 + il;
    const int bglob[2] = { bgA * 8 + warp, bgB * 8 + warp };

    float hold[2];
#pragma unroll
    for (int sec = 0; sec < 2; sec++) {
        hold[sec] = h0[(size_t)(dir * B_ + bglob[sec]) * H_ + iglob];
        __nv_bfloat16 hh2 = __float2bfloat16(hold[sec]);
        __nv_bfloat16 hl2 = __float2bfloat16(hold[sec] - __bfloat162float(hh2));
        int bg = sec ? bgB : bgA;
        st_cg_u16(&g_hh[dir][bg][0][warp][iglob], __bfloat16_as_ushort(hh2));
        st_cg_u16(&g_hl[dir][bg][0][warp][iglob], __bfloat16_as_ushort(hl2));
    }
    __syncwarp();
    if (lane == 0) { red_release_add(fown[0], 1); red_release_add(fown[1], 1); }

    const float bh_r = bhh[iglob];
    const float bh_z = bhh[512 + iglob];
    const float bh_n = bhh[1024 + iglob];

    __syncthreads();                         // w tiles ready

    // ldmatrix lane offset for A (weights), bytes.
    const uint32_t smb = smem_u32(smc);
    const uint32_t a_off = smb + (((lane & 15) * WST + 64 * warp + (lane >> 4) * 8) << 1);

    // Hoist wh A-fragments into registers (loop-invariant, shared by sections).
    uint32_t awh[6][4][4];
#pragma unroll
    for (int mt = 0; mt < 6; mt++)
#pragma unroll
        for (int k16 = 0; k16 < 4; k16++)
            LDSM4(awh[mt][k16], a_off + mt * (16 * WST * 2) + k16 * 32);

    const bool write_states = (out_size > T_ * B_ * 2 * H_);

    // B-frag direct-load mapping (R11-verified): b0 = h[n=lane>>2][2(lane&3)+{0,1}].
    const int boff = (lane >> 2) * 512 + 64 * warp + 2 * (lane & 3);
    const unsigned short* hbase[2] = { &g_hh[dir][bgA][0][0][0], &g_hh[dir][bgB][0][0][0] };
    const unsigned short* lbase[2] = { &g_hl[dir][bgA][0][0][0], &g_hl[dir][bgB][0][0][0] };

    const int sf = (2 * warp + (lane & 1)) * 8;

    for (int s = 0; s < T_; s++) {
        const int xrow = dir ? (T_ - 1 - s) : s;

        // gi for both sections, before any waits.
        float giv[2][3];
#pragma unroll
        for (int sec = 0; sec < 2; sec++) {
            const float* gp = gi + ((size_t)xrow * B_ + bglob[sec]) * G_ + iglob;
            giv[sec][0] = __ldcs(gp);
            giv[sec][1] = __ldcs(gp + 512);
            giv[sec][2] = __ldcs(gp + 1024);
        }

#pragma unroll
        for (int sec = 0; sec < 2; sec++) {
            // Per-warp acquire of this section's two source slices (tight spin).
            const unsigned target = basex[sec] + 8u * (unsigned)(s + 1);
            while (ld_acquire(gfl[sec] + sf) < target) { }
            __syncwarp();

            // B-fragments straight from L2.
            const unsigned short* ph = hbase[sec] + (s & 1) * 4096 + boff;
            const unsigned short* pl = lbase[sec] + (s & 1) * 4096 + boff;
            uint32_t bh[4][2], bl[4][2];
#pragma unroll
            for (int k16 = 0; k16 < 4; k16++) {
                bh[k16][0] = ld_cg_u32(ph + k16 * 16);
                bh[k16][1] = ld_cg_u32(ph + k16 * 16 + 8);
                bl[k16][0] = ld_cg_u32(pl + k16 * 16);
                bl[k16][1] = ld_cg_u32(pl + k16 * 16 + 8);
            }

            float acc[6][4];
#pragma unroll
            for (int mt = 0; mt < 6; mt++)
#pragma unroll
                for (int q = 0; q < 4; q++) acc[mt][q] = 0.f;

#pragma unroll
            for (int k16 = 0; k16 < 4; k16++) {
                const uint32_t koff = k16 * 32;
#pragma unroll
                for (int mt = 0; mt < 6; mt++) {
                    uint32_t al[4];
                    LDSM4(al, a_off + mt * (16 * WST * 2) + koff + WL_B);
                    MMA_BF16(acc[mt], awh[mt][k16], bh[k16][0], bh[k16][1]);
                    MMA_BF16(acc[mt], awh[mt][k16], bl[k16][0], bl[k16][1]);
                    MMA_BF16(acc[mt], al, bh[k16][0], bh[k16][1]);
                }
            }

            // 2-stage reduction (section-private buffer: no A/B WAR races).
            float* rb = red + sec * 3840 + (warp & 3) * 960;
            if (warp < 4) {
#pragma unroll
                for (int mt = 0; mt < 6; mt++) {
                    const int r = mt * 16 + (lane >> 2);
                    const int c = 2 * (lane & 3);
                    *(float2*)&rb[r * 10 + c]       = make_float2(acc[mt][0], acc[mt][1]);
                    *(float2*)&rb[(r + 8) * 10 + c] = make_float2(acc[mt][2], acc[mt][3]);
                }
            }
            __syncthreads();
            if (warp >= 4) {
#pragma unroll
                for (int mt = 0; mt < 6; mt++) {
                    const int r = mt * 16 + (lane >> 2);
                    const int c = 2 * (lane & 3);
                    float2 p0 = *(float2*)&rb[r * 10 + c];
                    float2 p1 = *(float2*)&rb[(r + 8) * 10 + c];
                    *(float2*)&rb[r * 10 + c] =
                        make_float2(p0.x + acc[mt][0], p0.y + acc[mt][1]);
                    *(float2*)&rb[(r + 8) * 10 + c] =
                        make_float2(p1.x + acc[mt][2], p1.y + acc[mt][3]);
                }
            }
            __syncthreads();

            // Epilogue (b = warp within this bg, il = lane).
            float ghr = bh_r, ghz = bh_z, ghn = bh_n;
#pragma unroll
            for (int q = 0; q < 4; q++) {
                const float* e = red + sec * 3840 + q * 960;
                ghr += e[il * 10 + warp];
                ghz += e[(32 + il) * 10 + warp];
                ghn += e[(64 + il) * 10 + warp];
            }

            const float rg = 1.f / (1.f + __expf(-(giv[sec][0] + ghr)));
            const float zg = 1.f / (1.f + __expf(-(giv[sec][1] + ghz)));
            const float ng = tanhf(giv[sec][2] + rg * ghn);
            const float hn = (1.f - zg) * ng + zg * hold[sec];
            hold[sec] = hn;

            // Publish split h(s+1); per-warp release-add (no block barrier).
            {
                const int bg = sec ? bgB : bgA;
                __nv_bfloat16 hh2 = __float2bfloat16(hn);
                __nv_bfloat16 hl2 = __float2bfloat16(hn - __bfloat162float(hh2));
                st_cg_u16(&g_hh[dir][bg][(s + 1) & 1][warp][iglob], __bfloat16_as_ushort(hh2));
                st_cg_u16(&g_hl[dir][bg][(s + 1) & 1][warp][iglob], __bfloat16_as_ushort(hl2));
            }
            __syncwarp();
            if (lane == 0) red_release_add(fown[sec], 1);

            // Off critical path: output stores.
            out[((size_t)s * B_ + bglob[sec]) * (2 * H_) + dir * H_ + iglob] = hold[sec];
            if (write_states && s == T_ - 1)
                out[(size_t)T_ * B_ * 2 * H_ +
                    (size_t)(dir * B_ + bglob[sec]) * H_ + iglob] = hold[sec];
        }
    }
}

// ---------------------------------------------------------------------------
extern "C" void kernel_launch(void* const* d_in, const int* in_sizes, int n_in,
                              void* d_out, int out_size)
{
    const float* x    = (const float*)d_in[0];
    const float* h0   = (const float*)d_in[1];
    const float* wihf = (const float*)d_in[2];
    const float* bihf = (const float*)d_in[3];
    const float* whhf = (const float*)d_in[4];
    const float* bhhf = (const float*)d_in[5];
    const float* wihr = (const float*)d_in[6];
    const float* bihr = (const float*)d_in[7];
    const float* whhr = (const float*)d_in[8];
    const float* bhhr = (const float*)d_in[9];
    float* out = (float*)d_out;

    __nv_bfloat16 *xh_p, *xl_p, *wh_p, *wl_p;
    cudaGetSymbolAddress((void**)&xh_p, g_xh);
    cudaGetSymbolAddress((void**)&xl_p, g_xl);
    cudaGetSymbolAddress((void**)&wh_p, g_wh);
    cudaGetSymbolAddress((void**)&wl_p, g_wl);

    {
        int n4 = (T_ * B_ * 512) / 4;
        conv_split<<<(n4 + 255) / 256, 256>>>((const float4*)x,
            (__nv_bfloat162*)xh_p, (__nv_bfloat162*)xl_p, n4);
        int w4 = (G_ * 512) / 4;
        conv_split<<<(w4 + 255) / 256, 256>>>((const float4*)wihf,
            (__nv_bfloat162*)wh_p, (__nv_bfloat162*)wl_p, w4);
        conv_split<<<(w4 + 255) / 256, 256>>>((const float4*)wihr,
            (__nv_bfloat162*)(wh_p + (size_t)G_ * 512),
            (__nv_bfloat162*)(wl_p + (size_t)G_ * 512), w4);
    }

    cudaFuncSetAttribute(gi_gemm_tc, cudaFuncAttributeMaxDynamicSharedMemorySize, GEMM_SMEM);
    dim3 g1(G_ / 128, (T_ * B_) / 128, 2);
    gi_gemm_tc<<<g1, 256, GEMM_SMEM>>>(bihf, bihr);

    cudaFuncSetAttribute(gru_rec, cudaFuncAttributeMaxDynamicSharedMemorySize, SMEM_REC);
    gru_rec<<<64, 256, SMEM_REC>>>(h0, whhf, bhhf, whhr, bhhr, out, out_size);
}

// round 16
// speedup vs baseline: 1.7187x; 1.7187x over previous
#include <cuda_runtime.h>
#include <cuda_bf16.h>
#include <cuda_fp16.h>
#include <cstdint>

// ---------------------------------------------------------------------------
// GRU_2602750181500: bidirectional GRU, T=2048, B=32, F=H=512, fp32.
// R16 = R12 (best, 8.52ms) with the recurrence MMA arithmetic switched to
//       fp16: A = w single fp16 (register-resident, 0 mainloop LDSM),
//       B = h split fp16 hi/lo (state stays fp32). 48 MMAs/warp/step (was 72).
//       GEMM/conv/protocol identical to R12.
// ---------------------------------------------------------------------------

#define T_ 2048
#define B_ 32
#define H_ 512
#define G_ 1536

__device__ __forceinline__ void st_release(unsigned* p, unsigned v) {
    asm volatile("st.release.gpu.global.u32 [%0], %1;" :: "l"(p), "r"(v) : "memory");
}
__device__ __forceinline__ unsigned ld_acquire(const unsigned* p) {
    unsigned v;
    asm volatile("ld.acquire.gpu.global.u32 %0, [%1];" : "=r"(v) : "l"(p) : "memory");
    return v;
}
__device__ __forceinline__ uint32_t smem_u32(const void* p) {
    uint32_t a;
    asm("{ .reg .u64 t; cvta.to.shared.u64 t, %1; cvt.u32.u64 %0, t; }"
        : "=r"(a) : "l"(p));
    return a;
}
__device__ __forceinline__ void st_cg_u16(unsigned short* p, unsigned short v) {
    asm volatile("st.global.cg.u16 [%0], %1;" :: "l"(p), "h"(v) : "memory");
}
__device__ __forceinline__ uint32_t ld_cg_u32(const unsigned short* p) {
    uint32_t v;
    asm volatile("ld.global.cg.u32 %0, [%1];" : "=r"(v) : "l"(p));
    return v;
}

#define LDSM4(r, addr) \
    asm volatile("ldmatrix.sync.aligned.m8n8.x4.shared.b16 {%0,%1,%2,%3}, [%4];" \
        : "=r"((r)[0]), "=r"((r)[1]), "=r"((r)[2]), "=r"((r)[3]) : "r"(addr))

#define MMA_BF16(d, a, b0, b1) \
    asm volatile("mma.sync.aligned.m16n8k16.row.col.f32.bf16.bf16.f32 " \
        "{%0,%1,%2,%3}, {%4,%5,%6,%7}, {%8,%9}, {%0,%1,%2,%3};" \
        : "+f"((d)[0]), "+f"((d)[1]), "+f"((d)[2]), "+f"((d)[3]) \
        : "r"((a)[0]), "r"((a)[1]), "r"((a)[2]), "r"((a)[3]), "r"(b0), "r"(b1))

#define MMA_F16(d, a, b0, b1) \
    asm volatile("mma.sync.aligned.m16n8k16.row.col.f32.f16.f16.f32 " \
        "{%0,%1,%2,%3}, {%4,%5,%6,%7}, {%8,%9}, {%0,%1,%2,%3};" \
        : "+f"((d)[0]), "+f"((d)[1]), "+f"((d)[2]), "+f"((d)[3]) \
        : "r"((a)[0]), "r"((a)[1]), "r"((a)[2]), "r"((a)[3]), "r"(b0), "r"(b1))

// Scratch (device globals: allocation-free rule).
__device__ float          g_gi[2][(size_t)T_ * B_ * G_];
__device__ unsigned short g_hh[2][4][2][8][512];   // h hi fp16 [dir][bg][pp][b][k]
__device__ unsigned short g_hl[2][4][2][8][512];   // h lo fp16
__device__ unsigned       g_flags[2][4][16 * 8];
__device__ __nv_bfloat16  g_xh[(size_t)T_ * B_ * 512];
__device__ __nv_bfloat16  g_xl[(size_t)T_ * B_ * 512];
__device__ __nv_bfloat16  g_wh[2][(size_t)G_ * 512];
__device__ __nv_bfloat16  g_wl[2][(size_t)G_ * 512];

// ---------------------------------------------------------------------------
// Split-conversion (GEMM inputs, bf16 — unchanged).
// ---------------------------------------------------------------------------
__global__ void conv_split(const float4* __restrict__ src,
                           __nv_bfloat162* __restrict__ hi,
                           __nv_bfloat162* __restrict__ lo, int n4)
{
    int i = blockIdx.x * blockDim.x + threadIdx.x;
    if (i >= n4) return;
    float4 v = src[i];
    __nv_bfloat16 h0 = __float2bfloat16(v.x), h1 = __float2bfloat16(v.y);
    __nv_bfloat16 h2 = __float2bfloat16(v.z), h3 = __float2bfloat16(v.w);
    hi[2 * i]     = __nv_bfloat162(h0, h1);
    hi[2 * i + 1] = __nv_bfloat162(h2, h3);
    lo[2 * i]     = __nv_bfloat162(__float2bfloat16(v.x - __bfloat162float(h0)),
                                   __float2bfloat16(v.y - __bfloat162float(h1)));
    lo[2 * i + 1] = __nv_bfloat162(__float2bfloat16(v.z - __bfloat162float(h2)),
                                   __float2bfloat16(v.w - __bfloat162float(h3)));
}

// ---------------------------------------------------------------------------
// Kernel 1: gi GEMM via HMMA (R12 version, register-prefetch 2-stage).
// ---------------------------------------------------------------------------
#define PADB 40
#define ARRE (128 * PADB)
#define ARRB (ARRE * 2)
#define STGB (4 * ARRB)
#define GEMM_SMEM (2 * STGB)

__global__ void __launch_bounds__(256, 1) gi_gemm_tc(
    const float* __restrict__ bf, const float* __restrict__ br)
{
    extern __shared__ __nv_bfloat16 sm[];

    const int tid  = threadIdx.x;
    const int lane = tid & 31;
    const int warp = tid >> 5;
    const int dir  = blockIdx.z;
    const int n0   = blockIdx.x * 128;
    const int m0   = blockIdx.y * 128;

    const __nv_bfloat16* __restrict__ xh = g_xh;
    const __nv_bfloat16* __restrict__ xl = g_xl;
    const __nv_bfloat16* __restrict__ wh = g_wh[dir];
    const __nv_bfloat16* __restrict__ wl = g_wl[dir];
    const float* __restrict__ bias = dir ? br : bf;
    float* __restrict__ gi = g_gi[dir];

    const int r0 = tid >> 2;
    const int c8 = (tid & 3) * 8;
    const __nv_bfloat16* pxh = xh + (size_t)(m0 + r0) * 512 + c8;
    const __nv_bfloat16* pxl = xl + (size_t)(m0 + r0) * 512 + c8;
    const __nv_bfloat16* pwh = wh + (size_t)(n0 + r0) * 512 + c8;
    const __nv_bfloat16* pwl = wl + (size_t)(n0 + r0) * 512 + c8;
    const size_t rstep = (size_t)64 * 512;

    const int so0 = r0 * PADB + c8;
    const int so1 = (r0 + 64) * PADB + c8;

    const int wm = warp >> 2, wn = warp & 3;
    const int a_row = wm * 64 + (lane & 15);
    const int a_off = (a_row * PADB + (lane >> 4) * 8) * 2;
    const int b_row = wn * 32 + (lane & 7) + ((lane >> 4) << 3);
    const int b_off = (b_row * PADB + ((lane >> 3) & 1) * 8) * 2;

    const uint32_t smb = smem_u32(sm);

    float acc[4][4][4];
#pragma unroll
    for (int i = 0; i < 4; i++)
#pragma unroll
        for (int j = 0; j < 4; j++)
#pragma unroll
            for (int q = 0; q < 4; q++) acc[i][j][q] = 0.f;

    float4 vh0, vh1, vl0, vl1, uh0, uh1, ul0, ul1;
    vh0 = *(const float4*)(pxh); vh1 = *(const float4*)(pxh + rstep);
    vl0 = *(const float4*)(pxl); vl1 = *(const float4*)(pxl + rstep);
    uh0 = *(const float4*)(pwh); uh1 = *(const float4*)(pwh + rstep);
    ul0 = *(const float4*)(pwl); ul1 = *(const float4*)(pwl + rstep);
    *(float4*)&sm[0 * ARRE + so0] = vh0; *(float4*)&sm[0 * ARRE + so1] = vh1;
    *(float4*)&sm[1 * ARRE + so0] = vl0; *(float4*)&sm[1 * ARRE + so1] = vl1;
    *(float4*)&sm[2 * ARRE + so0] = uh0; *(float4*)&sm[2 * ARRE + so1] = uh1;
    *(float4*)&sm[3 * ARRE + so0] = ul0; *(float4*)&sm[3 * ARRE + so1] = ul1;
    __syncthreads();

    for (int c = 0; c < 16; c++) {
        const int st = c & 1;
        if (c < 15) {
            const int k0 = (c + 1) * 32;
            vh0 = *(const float4*)(pxh + k0); vh1 = *(const float4*)(pxh + k0 + rstep);
            vl0 = *(const float4*)(pxl + k0); vl1 = *(const float4*)(pxl + k0 + rstep);
            uh0 = *(const float4*)(pwh + k0); uh1 = *(const float4*)(pwh + k0 + rstep);
            ul0 = *(const float4*)(pwl + k0); ul1 = *(const float4*)(pwl + k0 + rstep);
        }

        const uint32_t sb = smb + st * STGB;
#pragma unroll
        for (int kk = 0; kk < 2; kk++) {
            const uint32_t kby = kk * 32;
            uint32_t ah[4][4], al[4][4], bh[2][4], bl[2][4];
#pragma unroll
            for (int mt = 0; mt < 4; mt++) {
                LDSM4(ah[mt], sb + 0 * ARRB + a_off + mt * (16 * PADB * 2) + kby);
                LDSM4(al[mt], sb + 1 * ARRB + a_off + mt * (16 * PADB * 2) + kby);
            }
#pragma unroll
            for (int np = 0; np < 2; np++) {
                LDSM4(bh[np], sb + 2 * ARRB + b_off + np * (16 * PADB * 2) + kby);
                LDSM4(bl[np], sb + 3 * ARRB + b_off + np * (16 * PADB * 2) + kby);
            }
#pragma unroll
            for (int mt = 0; mt < 4; mt++) {
#pragma unroll
                for (int nt = 0; nt < 4; nt++) {
                    const int np = nt >> 1, hf = (nt & 1) * 2;
                    MMA_BF16(acc[mt][nt], ah[mt], bh[np][hf], bh[np][hf + 1]);
                    MMA_BF16(acc[mt][nt], ah[mt], bl[np][hf], bl[np][hf + 1]);
                    MMA_BF16(acc[mt][nt], al[mt], bh[np][hf], bh[np][hf + 1]);
                }
            }
        }
        __syncthreads();
        if (c < 15) {
            const int os = (st ^ 1) * (STGB / 2);
            *(float4*)&sm[os + 0 * ARRE + so0] = vh0; *(float4*)&sm[os + 0 * ARRE + so1] = vh1;
            *(float4*)&sm[os + 1 * ARRE + so0] = vl0; *(float4*)&sm[os + 1 * ARRE + so1] = vl1;
            *(float4*)&sm[os + 2 * ARRE + so0] = uh0; *(float4*)&sm[os + 2 * ARRE + so1] = uh1;
            *(float4*)&sm[os + 3 * ARRE + so0] = ul0; *(float4*)&sm[os + 3 * ARRE + so1] = ul1;
            __syncthreads();
        }
    }

#pragma unroll
    for (int mt = 0; mt < 4; mt++) {
        const int m = m0 + wm * 64 + mt * 16 + (lane >> 2);
#pragma unroll
        for (int nt = 0; nt < 4; nt++) {
            const int n = n0 + wn * 32 + nt * 8 + (lane & 3) * 2;
            const float b0 = bias[n], b1 = bias[n + 1];
            *(float2*)&gi[(size_t)m * G_ + n] =
                make_float2(acc[mt][nt][0] + b0, acc[mt][nt][1] + b1);
            *(float2*)&gi[(size_t)(m + 8) * G_ + n] =
                make_float2(acc[mt][nt][2] + b0, acc[mt][nt][3] + b1);
        }
    }
}

// ---------------------------------------------------------------------------
// Kernel 2: recurrence. fp16: w single (reg A-frags), h split hi/lo.
// SMEM: sw [96][520] fp16 | red f32 [4][960]
// ---------------------------------------------------------------------------
#define WST 520
#define RED_B (96 * WST * 2)                 // 99840 bytes
#define SMEM_REC (RED_B + 4 * 960 * 4)       // 115200 bytes

__global__ void __launch_bounds__(256, 1) gru_rec(
    const float* __restrict__ h0,
    const float* __restrict__ whh_f, const float* __restrict__ bhh_f,
    const float* __restrict__ whh_r, const float* __restrict__ bhh_r,
    float* __restrict__ out, int out_size)
{
    extern __shared__ char smc[];
    __half* sw = (__half*)smc;               // [96][520] fp16
    float* red = (float*)(smc + RED_B);      // [4][960]

    const int tid  = threadIdx.x;
    const int warp = tid >> 5;
    const int lane = tid & 31;
    const int bid = blockIdx.x;
    const int dir = bid >> 6;
    const int bg  = (bid >> 4) & 3;
    const int sl  = bid & 15;

    const float* __restrict__ whh = dir ? whh_r : whh_f;
    const float* __restrict__ bhh = dir ? bhh_r : bhh_f;
    const float* __restrict__ gi  = g_gi[dir];
    unsigned* flags = &g_flags[dir][bg][0];
    const unsigned base = ld_acquire(flags + sl * 8);

    // w_hh slice -> SMEM as single fp16.
    for (int idx = tid; idx < 96 * 512; idx += 256) {
        int r = idx >> 9, k = idx & 511;
        float v = whh[(size_t)((r >> 5) * 512 + sl * 32 + (r & 31)) * 512 + k];
        sw[r * WST + k] = __float2half(v);
    }

    const int il = lane;
    const int iglob = sl * 32 + il;
    const int bglob = bg * 8 + warp;

    float hold = h0[(size_t)(dir * B_ + bglob) * H_ + iglob];
    {
        __half hh2 = __float2half(hold);
        __half hl2 = __float2half(hold - __half2float(hh2));
        st_cg_u16(&g_hh[dir][bg][0][warp][iglob], __half_as_ushort(hh2));
        st_cg_u16(&g_hl[dir][bg][0][warp][iglob], __half_as_ushort(hl2));
    }

    const float bh_r = bhh[iglob];
    const float bh_z = bhh[512 + iglob];
    const float bh_n = bhh[1024 + iglob];

    __syncthreads();

    // ldmatrix lane offset for A (weights), bytes.
    const uint32_t smb = smem_u32(smc);
    const uint32_t a_off = smb + (((lane & 15) * WST + 64 * warp + (lane >> 4) * 8) << 1);

    // Hoist w A-fragments into registers (loop-invariant; single fp16).
    uint32_t aw[6][4][4];
#pragma unroll
    for (int mt = 0; mt < 6; mt++)
#pragma unroll
        for (int k16 = 0; k16 < 4; k16++)
            LDSM4(aw[mt][k16], a_off + mt * (16 * WST * 2) + k16 * 32);

    if (tid == 0) st_release(flags + sl * 8, base + 1);

    const bool write_states = (out_size > T_ * B_ * 2 * H_);

    // B-frag direct-load mapping (R11-verified): b0 = h[n=lane>>2][2(lane&3)+{0,1}].
    const int bn = lane >> 2;
    const int bk = 64 * warp + 2 * (lane & 3);
    const unsigned short* hhb = &g_hh[dir][bg][0][bn][bk];
    const unsigned short* hlb = &g_hl[dir][bg][0][bn][bk];
    const size_t ppo = (size_t)(&g_hh[0][0][1][0][0] - &g_hh[0][0][0][0][0]); // 4096

    const int src_flag = (2 * warp + (lane & 1)) * 8;

    for (int s = 0; s < T_; s++) {
        const int xrow = dir ? (T_ - 1 - s) : s;

        const float* gp = gi + ((size_t)xrow * B_ + bglob) * G_ + iglob;
        const float gir = __ldcs(gp);
        const float giz = __ldcs(gp + 512);
        const float gin = __ldcs(gp + 1024);

        // Per-warp acquire (tight spin).
        {
            const unsigned target = base + 1 + (unsigned)s;
            while (ld_acquire(flags + src_flag) < target) { }
            __syncwarp();
        }

        // B-fragments straight from L2 (16 u32 loads).
        const unsigned short* ph = hhb + (s & 1) * ppo;
        const unsigned short* pl = hlb + (s & 1) * ppo;
        uint32_t bh[4][2], bl[4][2];
#pragma unroll
        for (int k16 = 0; k16 < 4; k16++) {
            bh[k16][0] = ld_cg_u32(ph + k16 * 16);
            bh[k16][1] = ld_cg_u32(ph + k16 * 16 + 8);
            bl[k16][0] = ld_cg_u32(pl + k16 * 16);
            bl[k16][1] = ld_cg_u32(pl + k16 * 16 + 8);
        }

        float acc[6][4];
#pragma unroll
        for (int mt = 0; mt < 6; mt++)
#pragma unroll
            for (int q = 0; q < 4; q++) acc[mt][q] = 0.f;

#pragma unroll
        for (int k16 = 0; k16 < 4; k16++) {
#pragma unroll
            for (int mt = 0; mt < 6; mt++) {
                MMA_F16(acc[mt], aw[mt][k16], bh[k16][0], bh[k16][1]);
                MMA_F16(acc[mt], aw[mt][k16], bl[k16][0], bl[k16][1]);
            }
        }

        // 2-stage reduction of C partials: red[q][96][10].
        float* rb = red + (warp & 3) * 960;
        if (warp < 4) {
#pragma unroll
            for (int mt = 0; mt < 6; mt++) {
                const int r = mt * 16 + (lane >> 2);
                const int c = 2 * (lane & 3);
                *(float2*)&rb[r * 10 + c]       = make_float2(acc[mt][0], acc[mt][1]);
                *(float2*)&rb[(r + 8) * 10 + c] = make_float2(acc[mt][2], acc[mt][3]);
            }
        }
        __syncthreads();
        if (warp >= 4) {
#pragma unroll
            for (int mt = 0; mt < 6; mt++) {
                const int r = mt * 16 + (lane >> 2);
                const int c = 2 * (lane & 3);
                float2 p0 = *(float2*)&rb[r * 10 + c];
                float2 p1 = *(float2*)&rb[(r + 8) * 10 + c];
                *(float2*)&rb[r * 10 + c] =
                    make_float2(p0.x + acc[mt][0], p0.y + acc[mt][1]);
                *(float2*)&rb[(r + 8) * 10 + c] =
                    make_float2(p1.x + acc[mt][2], p1.y + acc[mt][3]);
            }
        }
        __syncthreads();

        float ghr = bh_r, ghz = bh_z, ghn = bh_n;
#pragma unroll
        for (int q = 0; q < 4; q++) {
            const float* e = red + q * 960;
            ghr += e[il * 10 + warp];
            ghz += e[(32 + il) * 10 + warp];
            ghn += e[(64 + il) * 10 + warp];
        }

        const float rg = 1.f / (1.f + __expf(-(gir + ghr)));
        const float zg = 1.f / (1.f + __expf(-(giz + ghz)));
        const float ng = tanhf(gin + rg * ghn);
        const float hn = (1.f - zg) * ng + zg * hold;
        hold = hn;

        // Publish split h(s+1) as fp16 hi/lo.
        {
            __half hh2 = __float2half(hn);
            __half hl2 = __float2half(hn - __half2float(hh2));
            st_cg_u16(&g_hh[dir][bg][(s + 1) & 1][warp][iglob], __half_as_ushort(hh2));
            st_cg_u16(&g_hl[dir][bg][(s + 1) & 1][warp][iglob], __half_as_ushort(hl2));
        }
        __syncthreads();
        if (tid == 0) st_release(flags + sl * 8, base + 2 + (unsigned)s);

        out[((size_t)s * B_ + bglob) * (2 * H_) + dir * H_ + iglob] = hn;
        if (write_states && s == T_ - 1)
            out[(size_t)T_ * B_ * 2 * H_ + (size_t)(dir * B_ + bglob) * H_ + iglob] = hn;
    }
}

// ---------------------------------------------------------------------------
extern "C" void kernel_launch(void* const* d_in, const int* in_sizes, int n_in,
                              void* d_out, int out_size)
{
    const float* x    = (const float*)d_in[0];
    const float* h0   = (const float*)d_in[1];
    const float* wihf = (const float*)d_in[2];
    const float* bihf = (const float*)d_in[3];
    const float* whhf = (const float*)d_in[4];
    const float* bhhf = (const float*)d_in[5];
    const float* wihr = (const float*)d_in[6];
    const float* bihr = (const float*)d_in[7];
    const float* whhr = (const float*)d_in[8];
    const float* bhhr = (const float*)d_in[9];
    float* out = (float*)d_out;

    __nv_bfloat16 *xh_p, *xl_p, *wh_p, *wl_p;
    cudaGetSymbolAddress((void**)&xh_p, g_xh);
    cudaGetSymbolAddress((void**)&xl_p, g_xl);
    cudaGetSymbolAddress((void**)&wh_p, g_wh);
    cudaGetSymbolAddress((void**)&wl_p, g_wl);

    {
        int n4 = (T_ * B_ * 512) / 4;
        conv_split<<<(n4 + 255) / 256, 256>>>((const float4*)x,
            (__nv_bfloat162*)xh_p, (__nv_bfloat162*)xl_p, n4);
        int w4 = (G_ * 512) / 4;
        conv_split<<<(w4 + 255) / 256, 256>>>((const float4*)wihf,
            (__nv_bfloat162*)wh_p, (__nv_bfloat162*)wl_p, w4);
        conv_split<<<(w4 + 255) / 256, 256>>>((const float4*)wihr,
            (__nv_bfloat162*)(wh_p + (size_t)G_ * 512),
            (__nv_bfloat162*)(wl_p + (size_t)G_ * 512), w4);
    }

    cudaFuncSetAttribute(gi_gemm_tc, cudaFuncAttributeMaxDynamicSharedMemorySize, GEMM_SMEM);
    dim3 g1(G_ / 128, (T_ * B_) / 128, 2);
    gi_gemm_tc<<<g1, 256, GEMM_SMEM>>>(bihf, bihr);

    cudaFuncSetAttribute(gru_rec, cudaFuncAttributeMaxDynamicSharedMemorySize, SMEM_REC);
    gru_rec<<<128, 256, SMEM_REC>>>(h0, whhf, bhhf, whhr, bhhr, out, out_size);
}

// round 17
// speedup vs baseline: 1.7801x; 1.0357x over previous
#include <cuda_runtime.h>
#include <cuda_bf16.h>
#include <cuda_fp16.h>
#include <cstdint>

// ---------------------------------------------------------------------------
// GRU_2602750181500: bidirectional GRU, T=2048, B=32, F=H=512, fp32.
// R17 = R16 (best, 8.15ms, rel_err 7.2e-5) with the h-lo split term dropped:
//       recurrence MMA is now w fp16 (register A-frags) x h fp16 single.
//       24 MMAs/warp/step (was 48), 8 B-frag loads (was 16), publish 1 u16.
//       Error budget: measured 4x gh->output damping => predicted ~2e-4 final.
//       GEMM/conv/protocol identical to R16.
// ---------------------------------------------------------------------------

#define T_ 2048
#define B_ 32
#define H_ 512
#define G_ 1536

__device__ __forceinline__ void st_release(unsigned* p, unsigned v) {
    asm volatile("st.release.gpu.global.u32 [%0], %1;" :: "l"(p), "r"(v) : "memory");
}
__device__ __forceinline__ unsigned ld_acquire(const unsigned* p) {
    unsigned v;
    asm volatile("ld.acquire.gpu.global.u32 %0, [%1];" : "=r"(v) : "l"(p) : "memory");
    return v;
}
__device__ __forceinline__ uint32_t smem_u32(const void* p) {
    uint32_t a;
    asm("{ .reg .u64 t; cvta.to.shared.u64 t, %1; cvt.u32.u64 %0, t; }"
        : "=r"(a) : "l"(p));
    return a;
}
__device__ __forceinline__ void st_cg_u16(unsigned short* p, unsigned short v) {
    asm volatile("st.global.cg.u16 [%0], %1;" :: "l"(p), "h"(v) : "memory");
}
__device__ __forceinline__ uint32_t ld_cg_u32(const unsigned short* p) {
    uint32_t v;
    asm volatile("ld.global.cg.u32 %0, [%1];" : "=r"(v) : "l"(p));
    return v;
}

#define LDSM4(r, addr) \
    asm volatile("ldmatrix.sync.aligned.m8n8.x4.shared.b16 {%0,%1,%2,%3}, [%4];" \
        : "=r"((r)[0]), "=r"((r)[1]), "=r"((r)[2]), "=r"((r)[3]) : "r"(addr))

#define MMA_BF16(d, a, b0, b1) \
    asm volatile("mma.sync.aligned.m16n8k16.row.col.f32.bf16.bf16.f32 " \
        "{%0,%1,%2,%3}, {%4,%5,%6,%7}, {%8,%9}, {%0,%1,%2,%3};" \
        : "+f"((d)[0]), "+f"((d)[1]), "+f"((d)[2]), "+f"((d)[3]) \
        : "r"((a)[0]), "r"((a)[1]), "r"((a)[2]), "r"((a)[3]), "r"(b0), "r"(b1))

#define MMA_F16(d, a, b0, b1) \
    asm volatile("mma.sync.aligned.m16n8k16.row.col.f32.f16.f16.f32 " \
        "{%0,%1,%2,%3}, {%4,%5,%6,%7}, {%8,%9}, {%0,%1,%2,%3};" \
        : "+f"((d)[0]), "+f"((d)[1]), "+f"((d)[2]), "+f"((d)[3]) \
        : "r"((a)[0]), "r"((a)[1]), "r"((a)[2]), "r"((a)[3]), "r"(b0), "r"(b1))

// Scratch (device globals: allocation-free rule).
__device__ float          g_gi[2][(size_t)T_ * B_ * G_];
__device__ unsigned short g_hh[2][4][2][8][512];   // h fp16 [dir][bg][pp][b][k]
__device__ unsigned       g_flags[2][4][16 * 8];
__device__ __nv_bfloat16  g_xh[(size_t)T_ * B_ * 512];
__device__ __nv_bfloat16  g_xl[(size_t)T_ * B_ * 512];
__device__ __nv_bfloat16  g_wh[2][(size_t)G_ * 512];
__device__ __nv_bfloat16  g_wl[2][(size_t)G_ * 512];

// ---------------------------------------------------------------------------
// Split-conversion (GEMM inputs, bf16 — unchanged).
// ---------------------------------------------------------------------------
__global__ void conv_split(const float4* __restrict__ src,
                           __nv_bfloat162* __restrict__ hi,
                           __nv_bfloat162* __restrict__ lo, int n4)
{
    int i = blockIdx.x * blockDim.x + threadIdx.x;
    if (i >= n4) return;
    float4 v = src[i];
    __nv_bfloat16 h0 = __float2bfloat16(v.x), h1 = __float2bfloat16(v.y);
    __nv_bfloat16 h2 = __float2bfloat16(v.z), h3 = __float2bfloat16(v.w);
    hi[2 * i]     = __nv_bfloat162(h0, h1);
    hi[2 * i + 1] = __nv_bfloat162(h2, h3);
    lo[2 * i]     = __nv_bfloat162(__float2bfloat16(v.x - __bfloat162float(h0)),
                                   __float2bfloat16(v.y - __bfloat162float(h1)));
    lo[2 * i + 1] = __nv_bfloat162(__float2bfloat16(v.z - __bfloat162float(h2)),
                                   __float2bfloat16(v.w - __bfloat162float(h3)));
}

// ---------------------------------------------------------------------------
// Kernel 1: gi GEMM via HMMA (R12 version, register-prefetch 2-stage).
// ---------------------------------------------------------------------------
#define PADB 40
#define ARRE (128 * PADB)
#define ARRB (ARRE * 2)
#define STGB (4 * ARRB)
#define GEMM_SMEM (2 * STGB)

__global__ void __launch_bounds__(256, 1) gi_gemm_tc(
    const float* __restrict__ bf, const float* __restrict__ br)
{
    extern __shared__ __nv_bfloat16 sm[];

    const int tid  = threadIdx.x;
    const int lane = tid & 31;
    const int warp = tid >> 5;
    const int dir  = blockIdx.z;
    const int n0   = blockIdx.x * 128;
    const int m0   = blockIdx.y * 128;

    const __nv_bfloat16* __restrict__ xh = g_xh;
    const __nv_bfloat16* __restrict__ xl = g_xl;
    const __nv_bfloat16* __restrict__ wh = g_wh[dir];
    const __nv_bfloat16* __restrict__ wl = g_wl[dir];
    const float* __restrict__ bias = dir ? br : bf;
    float* __restrict__ gi = g_gi[dir];

    const int r0 = tid >> 2;
    const int c8 = (tid & 3) * 8;
    const __nv_bfloat16* pxh = xh + (size_t)(m0 + r0) * 512 + c8;
    const __nv_bfloat16* pxl = xl + (size_t)(m0 + r0) * 512 + c8;
    const __nv_bfloat16* pwh = wh + (size_t)(n0 + r0) * 512 + c8;
    const __nv_bfloat16* pwl = wl + (size_t)(n0 + r0) * 512 + c8;
    const size_t rstep = (size_t)64 * 512;

    const int so0 = r0 * PADB + c8;
    const int so1 = (r0 + 64) * PADB + c8;

    const int wm = warp >> 2, wn = warp & 3;
    const int a_row = wm * 64 + (lane & 15);
    const int a_off = (a_row * PADB + (lane >> 4) * 8) * 2;
    const int b_row = wn * 32 + (lane & 7) + ((lane >> 4) << 3);
    const int b_off = (b_row * PADB + ((lane >> 3) & 1) * 8) * 2;

    const uint32_t smb = smem_u32(sm);

    float acc[4][4][4];
#pragma unroll
    for (int i = 0; i < 4; i++)
#pragma unroll
        for (int j = 0; j < 4; j++)
#pragma unroll
            for (int q = 0; q < 4; q++) acc[i][j][q] = 0.f;

    float4 vh0, vh1, vl0, vl1, uh0, uh1, ul0, ul1;
    vh0 = *(const float4*)(pxh); vh1 = *(const float4*)(pxh + rstep);
    vl0 = *(const float4*)(pxl); vl1 = *(const float4*)(pxl + rstep);
    uh0 = *(const float4*)(pwh); uh1 = *(const float4*)(pwh + rstep);
    ul0 = *(const float4*)(pwl); ul1 = *(const float4*)(pwl + rstep);
    *(float4*)&sm[0 * ARRE + so0] = vh0; *(float4*)&sm[0 * ARRE + so1] = vh1;
    *(float4*)&sm[1 * ARRE + so0] = vl0; *(float4*)&sm[1 * ARRE + so1] = vl1;
    *(float4*)&sm[2 * ARRE + so0] = uh0; *(float4*)&sm[2 * ARRE + so1] = uh1;
    *(float4*)&sm[3 * ARRE + so0] = ul0; *(float4*)&sm[3 * ARRE + so1] = ul1;
    __syncthreads();

    for (int c = 0; c < 16; c++) {
        const int st = c & 1;
        if (c < 15) {
            const int k0 = (c + 1) * 32;
            vh0 = *(const float4*)(pxh + k0); vh1 = *(const float4*)(pxh + k0 + rstep);
            vl0 = *(const float4*)(pxl + k0); vl1 = *(const float4*)(pxl + k0 + rstep);
            uh0 = *(const float4*)(pwh + k0); uh1 = *(const float4*)(pwh + k0 + rstep);
            ul0 = *(const float4*)(pwl + k0); ul1 = *(const float4*)(pwl + k0 + rstep);
        }

        const uint32_t sb = smb + st * STGB;
#pragma unroll
        for (int kk = 0; kk < 2; kk++) {
            const uint32_t kby = kk * 32;
            uint32_t ah[4][4], al[4][4], bh[2][4], bl[2][4];
#pragma unroll
            for (int mt = 0; mt < 4; mt++) {
                LDSM4(ah[mt], sb + 0 * ARRB + a_off + mt * (16 * PADB * 2) + kby);
                LDSM4(al[mt], sb + 1 * ARRB + a_off + mt * (16 * PADB * 2) + kby);
            }
#pragma unroll
            for (int np = 0; np < 2; np++) {
                LDSM4(bh[np], sb + 2 * ARRB + b_off + np * (16 * PADB * 2) + kby);
                LDSM4(bl[np], sb + 3 * ARRB + b_off + np * (16 * PADB * 2) + kby);
            }
#pragma unroll
            for (int mt = 0; mt < 4; mt++) {
#pragma unroll
                for (int nt = 0; nt < 4; nt++) {
                    const int np = nt >> 1, hf = (nt & 1) * 2;
                    MMA_BF16(acc[mt][nt], ah[mt], bh[np][hf], bh[np][hf + 1]);
                    MMA_BF16(acc[mt][nt], ah[mt], bl[np][hf], bl[np][hf + 1]);
                    MMA_BF16(acc[mt][nt], al[mt], bh[np][hf], bh[np][hf + 1]);
                }
            }
        }
        __syncthreads();
        if (c < 15) {
            const int os = (st ^ 1) * (STGB / 2);
            *(float4*)&sm[os + 0 * ARRE + so0] = vh0; *(float4*)&sm[os + 0 * ARRE + so1] = vh1;
            *(float4*)&sm[os + 1 * ARRE + so0] = vl0; *(float4*)&sm[os + 1 * ARRE + so1] = vl1;
            *(float4*)&sm[os + 2 * ARRE + so0] = uh0; *(float4*)&sm[os + 2 * ARRE + so1] = uh1;
            *(float4*)&sm[os + 3 * ARRE + so0] = ul0; *(float4*)&sm[os + 3 * ARRE + so1] = ul1;
            __syncthreads();
        }
    }

#pragma unroll
    for (int mt = 0; mt < 4; mt++) {
        const int m = m0 + wm * 64 + mt * 16 + (lane >> 2);
#pragma unroll
        for (int nt = 0; nt < 4; nt++) {
            const int n = n0 + wn * 32 + nt * 8 + (lane & 3) * 2;
            const float b0 = bias[n], b1 = bias[n + 1];
            *(float2*)&gi[(size_t)m * G_ + n] =
                make_float2(acc[mt][nt][0] + b0, acc[mt][nt][1] + b1);
            *(float2*)&gi[(size_t)(m + 8) * G_ + n] =
                make_float2(acc[mt][nt][2] + b0, acc[mt][nt][3] + b1);
        }
    }
}

// ---------------------------------------------------------------------------
// Kernel 2: recurrence. fp16 w (reg A-frags) x fp16 h (single).
// SMEM: sw [96][520] fp16 | red f32 [4][960]
// ---------------------------------------------------------------------------
#define WST 520
#define RED_B (96 * WST * 2)                 // 99840 bytes
#define SMEM_REC (RED_B + 4 * 960 * 4)       // 115200 bytes

__global__ void __launch_bounds__(256, 1) gru_rec(
    const float* __restrict__ h0,
    const float* __restrict__ whh_f, const float* __restrict__ bhh_f,
    const float* __restrict__ whh_r, const float* __restrict__ bhh_r,
    float* __restrict__ out, int out_size)
{
    extern __shared__ char smc[];
    __half* sw = (__half*)smc;               // [96][520] fp16
    float* red = (float*)(smc + RED_B);      // [4][960]

    const int tid  = threadIdx.x;
    const int warp = tid >> 5;
    const int lane = tid & 31;
    const int bid = blockIdx.x;
    const int dir = bid >> 6;
    const int bg  = (bid >> 4) & 3;
    const int sl  = bid & 15;

    const float* __restrict__ whh = dir ? whh_r : whh_f;
    const float* __restrict__ bhh = dir ? bhh_r : bhh_f;
    const float* __restrict__ gi  = g_gi[dir];
    unsigned* flags = &g_flags[dir][bg][0];
    const unsigned base = ld_acquire(flags + sl * 8);

    // w_hh slice -> SMEM as single fp16.
    for (int idx = tid; idx < 96 * 512; idx += 256) {
        int r = idx >> 9, k = idx & 511;
        float v = whh[(size_t)((r >> 5) * 512 + sl * 32 + (r & 31)) * 512 + k];
        sw[r * WST + k] = __float2half(v);
    }

    const int il = lane;
    const int iglob = sl * 32 + il;
    const int bglob = bg * 8 + warp;

    float hold = h0[(size_t)(dir * B_ + bglob) * H_ + iglob];
    st_cg_u16(&g_hh[dir][bg][0][warp][iglob],
              __half_as_ushort(__float2half(hold)));

    const float bh_r = bhh[iglob];
    const float bh_z = bhh[512 + iglob];
    const float bh_n = bhh[1024 + iglob];

    __syncthreads();

    // ldmatrix lane offset for A (weights), bytes.
    const uint32_t smb = smem_u32(smc);
    const uint32_t a_off = smb + (((lane & 15) * WST + 64 * warp + (lane >> 4) * 8) << 1);

    // Hoist w A-fragments into registers (loop-invariant; single fp16).
    uint32_t aw[6][4][4];
#pragma unroll
    for (int mt = 0; mt < 6; mt++)
#pragma unroll
        for (int k16 = 0; k16 < 4; k16++)
            LDSM4(aw[mt][k16], a_off + mt * (16 * WST * 2) + k16 * 32);

    if (tid == 0) st_release(flags + sl * 8, base + 1);

    const bool write_states = (out_size > T_ * B_ * 2 * H_);

    // B-frag direct-load mapping: b0 = h[n=lane>>2][2(lane&3)+{0,1}], b1 = +8k.
    const int bn = lane >> 2;
    const int bk = 64 * warp + 2 * (lane & 3);
    const unsigned short* hhb = &g_hh[dir][bg][0][bn][bk];
    const size_t ppo = (size_t)(&g_hh[0][0][1][0][0] - &g_hh[0][0][0][0][0]); // 4096

    const int src_flag = (2 * warp + (lane & 1)) * 8;

    for (int s = 0; s < T_; s++) {
        const int xrow = dir ? (T_ - 1 - s) : s;

        const float* gp = gi + ((size_t)xrow * B_ + bglob) * G_ + iglob;
        const float gir = __ldcs(gp);
        const float giz = __ldcs(gp + 512);
        const float gin = __ldcs(gp + 1024);

        // Per-warp acquire (tight spin).
        {
            const unsigned target = base + 1 + (unsigned)s;
            while (ld_acquire(flags + src_flag) < target) { }
            __syncwarp();
        }

        // B-fragments straight from L2 (8 u32 loads).
        const unsigned short* ph = hhb + (s & 1) * ppo;
        uint32_t bh[4][2];
#pragma unroll
        for (int k16 = 0; k16 < 4; k16++) {
            bh[k16][0] = ld_cg_u32(ph + k16 * 16);
            bh[k16][1] = ld_cg_u32(ph + k16 * 16 + 8);
        }

        float acc[6][4];
#pragma unroll
        for (int mt = 0; mt < 6; mt++)
#pragma unroll
            for (int q = 0; q < 4; q++) acc[mt][q] = 0.f;

#pragma unroll
        for (int k16 = 0; k16 < 4; k16++) {
#pragma unroll
            for (int mt = 0; mt < 6; mt++)
                MMA_F16(acc[mt], aw[mt][k16], bh[k16][0], bh[k16][1]);
        }

        // 2-stage reduction of C partials: red[q][96][10].
        float* rb = red + (warp & 3) * 960;
        if (warp < 4) {
#pragma unroll
            for (int mt = 0; mt < 6; mt++) {
                const int r = mt * 16 + (lane >> 2);
                const int c = 2 * (lane & 3);
                *(float2*)&rb[r * 10 + c]       = make_float2(acc[mt][0], acc[mt][1]);
                *(float2*)&rb[(r + 8) * 10 + c] = make_float2(acc[mt][2], acc[mt][3]);
            }
        }
        __syncthreads();
        if (warp >= 4) {
#pragma unroll
            for (int mt = 0; mt < 6; mt++) {
                const int r = mt * 16 + (lane >> 2);
                const int c = 2 * (lane & 3);
                float2 p0 = *(float2*)&rb[r * 10 + c];
                float2 p1 = *(float2*)&rb[(r + 8) * 10 + c];
                *(float2*)&rb[r * 10 + c] =
                    make_float2(p0.x + acc[mt][0], p0.y + acc[mt][1]);
                *(float2*)&rb[(r + 8) * 10 + c] =
                    make_float2(p1.x + acc[mt][2], p1.y + acc[mt][3]);
            }
        }
        __syncthreads();

        float ghr = bh_r, ghz = bh_z, ghn = bh_n;
#pragma unroll
        for (int q = 0; q < 4; q++) {
            const float* e = red + q * 960;
            ghr += e[il * 10 + warp];
            ghz += e[(32 + il) * 10 + warp];
            ghn += e[(64 + il) * 10 + warp];
        }

        const float rg = 1.f / (1.f + __expf(-(gir + ghr)));
        const float zg = 1.f / (1.f + __expf(-(giz + ghz)));
        const float ng = tanhf(gin + rg * ghn);
        const float hn = (1.f - zg) * ng + zg * hold;
        hold = hn;

        // Publish h(s+1) as single fp16.
        st_cg_u16(&g_hh[dir][bg][(s + 1) & 1][warp][iglob],
                  __half_as_ushort(__float2half(hn)));
        __syncthreads();
        if (tid == 0) st_release(flags + sl * 8, base + 2 + (unsigned)s);

        out[((size_t)s * B_ + bglob) * (2 * H_) + dir * H_ + iglob] = hn;
        if (write_states && s == T_ - 1)
            out[(size_t)T_ * B_ * 2 * H_ + (size_t)(dir * B_ + bglob) * H_ + iglob] = hn;
    }
}

// ---------------------------------------------------------------------------
extern "C" void kernel_launch(void* const* d_in, const int* in_sizes, int n_in,
                              void* d_out, int out_size)
{
    const float* x    = (const float*)d_in[0];
    const float* h0   = (const float*)d_in[1];
    const float* wihf = (const float*)d_in[2];
    const float* bihf = (const float*)d_in[3];
    const float* whhf = (const float*)d_in[4];
    const float* bhhf = (const float*)d_in[5];
    const float* wihr = (const float*)d_in[6];
    const float* bihr = (const float*)d_in[7];
    const float* whhr = (const float*)d_in[8];
    const float* bhhr = (const float*)d_in[9];
    float* out = (float*)d_out;

    __nv_bfloat16 *xh_p, *xl_p, *wh_p, *wl_p;
    cudaGetSymbolAddress((void**)&xh_p, g_xh);
    cudaGetSymbolAddress((void**)&xl_p, g_xl);
    cudaGetSymbolAddress((void**)&wh_p, g_wh);
    cudaGetSymbolAddress((void**)&wl_p, g_wl);

    {
        int n4 = (T_ * B_ * 512) / 4;
        conv_split<<<(n4 + 255) / 256, 256>>>((const float4*)x,
            (__nv_bfloat162*)xh_p, (__nv_bfloat162*)xl_p, n4);
        int w4 = (G_ * 512) / 4;
        conv_split<<<(w4 + 255) / 256, 256>>>((const float4*)wihf,
            (__nv_bfloat162*)wh_p, (__nv_bfloat162*)wl_p, w4);
        conv_split<<<(w4 + 255) / 256, 256>>>((const float4*)wihr,
            (__nv_bfloat162*)(wh_p + (size_t)G_ * 512),
            (__nv_bfloat162*)(wl_p + (size_t)G_ * 512), w4);
    }

    cudaFuncSetAttribute(gi_gemm_tc, cudaFuncAttributeMaxDynamicSharedMemorySize, GEMM_SMEM);
    dim3 g1(G_ / 128, (T_ * B_) / 128, 2);
    gi_gemm_tc<<<g1, 256, GEMM_SMEM>>>(bihf, bihr);

    cudaFuncSetAttribute(gru_rec, cudaFuncAttributeMaxDynamicSharedMemorySize, SMEM_REC);
    gru_rec<<<128, 256, SMEM_REC>>>(h0, whhf, bhhf, whhr, bhhr, out, out_size);
}